// round 17
// baseline (speedup 1.0000x reference)
#include <cuda_runtime.h>
#include <cuda_fp16.h>

#define B_   128
#define S_   512
#define D_   256
#define H_   512
#define ODIM 1275
#define NCTA 128

typedef unsigned long long u64;
typedef unsigned int u32;

// ---------------- persistent device scratch (pre-swizzled f16 tiles) ----------
__device__ __align__(256) unsigned char g_xs[S_][2][32768];    // x: [t][ch]
__device__ __align__(256) unsigned char g_h0s[2][4][32768];    // h0: [buf][ch]
__device__ __align__(256) unsigned char g_h1s[2][4][32768];
__device__ __align__(256) unsigned char g_W0s[64][6][8192];    // [jt][ch] 32n x 128k
__device__ __align__(256) unsigned char g_W1s[64][8][8192];
__device__ unsigned g_flags[NCTA * 32];

// ---------------- helpers ----------------
__device__ __forceinline__ u32 smem_u32(const void* p) {
    u32 a; asm("{ .reg .u64 t; cvta.to.shared.u64 t, %1; cvt.u32.u64 %0, t; }" : "=r"(a) : "l"(p));
    return a;
}
__device__ __forceinline__ float ex2f(float x) { float y; asm("ex2.approx.ftz.f32 %0, %1;" : "=f"(y) : "f"(x)); return y; }
__device__ __forceinline__ float rcpf(float x) { float y; asm("rcp.approx.ftz.f32 %0, %1;" : "=f"(y) : "f"(x)); return y; }
__device__ __forceinline__ float fsig(float z)  { return rcpf(1.f + ex2f(-1.44269504088896f * z)); }
__device__ __forceinline__ float ftanh(float z) { return 1.f - 2.f * rcpf(1.f + ex2f(2.88539008177793f * z)); }

__device__ __forceinline__ void cp16(void* dst, const void* src) {
    u32 d = smem_u32(dst);
    asm volatile("cp.async.cg.shared.global [%0], [%1], 16;\n" :: "r"(d), "l"(src));
}
__device__ __forceinline__ void cp_commit() { asm volatile("cp.async.commit_group;\n" ::); }
#define CP_WAIT0() asm volatile("cp.async.wait_group 0;\n" ::)
#define CP_WAIT1() asm volatile("cp.async.wait_group 1;\n" ::)

#define LDM4(r0, r1, r2, r3, addr) \
    asm volatile("ldmatrix.sync.aligned.m8n8.x4.shared.b16 {%0,%1,%2,%3}, [%4];" \
        : "=r"(r0), "=r"(r1), "=r"(r2), "=r"(r3) : "r"(addr))

#define LDM2(r0, r1, addr) \
    asm volatile("ldmatrix.sync.aligned.m8n8.x2.shared.b16 {%0,%1}, [%2];" \
        : "=r"(r0), "=r"(r1) : "r"(addr))

#define MMA4(d, A0, A1, A2, A3, B0, B1) \
    asm volatile("mma.sync.aligned.m16n8k16.row.col.f32.f16.f16.f32 " \
        "{%0,%1,%2,%3}, {%4,%5,%6,%7}, {%8,%9}, {%0,%1,%2,%3};" \
        : "+f"((d)[0]), "+f"((d)[1]), "+f"((d)[2]), "+f"((d)[3]) \
        : "r"(A0), "r"(A1), "r"(A2), "r"(A3), "r"(B0), "r"(B1))

// ---------------- grid-wide barrier (per-CTA flag slots) ----------------
__device__ __forceinline__ void grid_sync_flag(int cta, int tid, unsigned gen) {
    __syncthreads();
    if (tid == 0) {
        __threadfence();
        *((volatile unsigned*)&g_flags[cta * 32]) = gen;
    }
    if (tid < NCTA) {
        while (*((volatile unsigned*)&g_flags[tid * 32]) < gen) { }
    }
    __threadfence();
    __syncthreads();
}

// swizzled element offset inside a [rows][128k] f16 tile
__device__ __forceinline__ u32 swzoff(int row, int k) {
    return (u32)row * 256u + ((((u32)(k >> 3)) ^ ((u32)row & 7u)) << 4) + (((u32)k & 7u) << 1);
}

// ---------------- prep: f16-convert + swizzle x, W; zero h ----------------
__global__ void prep_kernel(const float* __restrict__ x,
                            const float* __restrict__ W0,
                            const float* __restrict__ W1)
{
    const int stride = gridDim.x * blockDim.x;
    const int t0 = blockIdx.x * blockDim.x + threadIdx.x;

    if (t0 < NCTA * 32) g_flags[t0] = 0u;

    for (int i = t0; i < 2 * 4 * 32768 / 4; i += stride) {
        ((u32*)g_h0s)[i] = 0u;
        ((u32*)g_h1s)[i] = 0u;
    }
    for (int idx = t0; idx < S_ * 2 * 128 * 128; idx += stride) {
        int t   = idx / (2 * 128 * 128);
        int rem = idx % (2 * 128 * 128);
        int ch  = rem / (128 * 128);
        int b   = (rem / 128) % 128;
        int k   = rem % 128;
        float v = x[(b * S_ + t) * D_ + ch * 128 + k];
        *(__half*)(&g_xs[t][ch][swzoff(b, k)]) = __float2half_rn(v);
    }
    for (int idx = t0; idx < 64 * 6 * 32 * 128; idx += stride) {
        int jt  = idx / (6 * 32 * 128);
        int rem = idx % (6 * 32 * 128);
        int ch  = rem / (32 * 128);
        int n   = (rem / 128) % 32;
        int k   = rem % 128;
        float v = W0[(ch * 128 + k) * 2048 + (n >> 3) * 512 + jt * 8 + (n & 7)];
        *(__half*)(&g_W0s[jt][ch][swzoff(n, k)]) = __float2half_rn(v);
    }
    for (int idx = t0; idx < 64 * 8 * 32 * 128; idx += stride) {
        int jt  = idx / (8 * 32 * 128);
        int rem = idx % (8 * 32 * 128);
        int ch  = rem / (32 * 128);
        int n   = (rem / 128) % 32;
        int k   = rem % 128;
        float v = W1[(ch * 128 + k) * 2048 + (n >> 3) * 512 + jt * 8 + (n & 7)];
        *(__half*)(&g_W1s[jt][ch][swzoff(n, k)]) = __float2half_rn(v);
    }
}

// ---------------- 32KB group stage: two 16KB batch-half chunks, 1 cp group ----
__device__ __forceinline__ void stage32(unsigned char* dst,
                                        const unsigned char* sA,
                                        const unsigned char* sB, int tid) {
    #pragma unroll
    for (int i = 0; i < 4; i++) { int o = (tid + (i << 8)) << 4; cp16(dst + o, sA + o); }
    #pragma unroll
    for (int i = 0; i < 4; i++) { int o = (tid + (i << 8)) << 4; cp16(dst + 16384 + o, sB + o); }
    cp_commit();
}

// ---------------- per-lane ldmatrix/mma context ----------------
struct LaneCtx { u32 sA, rA, kgA, rB, kgB; };

// one K=128 chunk of D[M=32 cols][N=64 b]; per-warp m32 x n8.
__device__ __forceinline__ void mma_chunk(u32 ab, u32 wb, float* acc, const LaneCtx& L) {
    const u32 aB0 = wb + L.rA * 256u;
    const u32 aB1 = aB0 + 4096u;              // +16 weight rows
    const u32 bB  = ab + L.rB * 256u;
    #pragma unroll
    for (int j = 0; j < 8; j++) {
        u32 kiA = ((((u32)(2 * j)) | L.kgA) ^ L.sA) << 4;
        u32 kiB = ((((u32)(2 * j)) | L.kgB) ^ (L.rB & 7u)) << 4;
        u32 a0, a1, a2, a3, e0, e1, e2, e3, b0, b1;
        LDM4(a0, a1, a2, a3, aB0 + kiA);
        LDM4(e0, e1, e2, e3, aB1 + kiA);
        LDM2(b0, b1, bB + kiB);
        MMA4(acc + 0, a0, a1, a2, a3, b0, b1);
        MMA4(acc + 4, e0, e1, e2, e3, b0, b1);
    }
}

// group = 2 k-chunks
__device__ __forceinline__ void mma2(u32 ab, u32 wb, float* acc, const LaneCtx& L) {
    mma_chunk(ab, wb, acc, L);
    mma_chunk(ab + 16384u, wb + 8192u, acc, L);
}

// ---------------- epilogue: in-register gates, f16 h store ----------------
__device__ __forceinline__ void epilogue(
    const float* acc, float* cst, float4 bias,
    unsigned char* hdst, u32 cj, int lane, int warp, int u, int bh)
{
    #pragma unroll
    for (int e = 0; e < 2; e++) {
        float zi = acc[e]     + bias.x;
        float zf = acc[2 + e] + bias.y;
        float zg = acc[4 + e] + bias.z;
        float zo = acc[6 + e] + bias.w;
        float c  = cst[e];
        float cn = fsig(zf) * c + fsig(zi) * ftanh(zg);
        cst[e] = cn;
        float h = fsig(zo) * ftanh(cn);
        int b = bh * 64 + warp * 8 + (lane & 3) * 2 + e;
        u32 off = (u32)b * 256u + ((cj ^ ((u32)b & 7u)) << 4) + (u32)u * 2u;
        *(__half*)(hdst + off) = __float2half_rn(h);
    }
}

#define ADV3(v) do { if (++(v) == 3) (v) = 0; } while (0)
#define ACCZ(a) do { _Pragma("unroll") for (int _i = 0; _i < 8; _i++) (a)[_i] = 0.f; } while (0)

// ---------------- persistent main kernel: 128 CTAs x 256 threads ----------------
__global__ void __launch_bounds__(256, 1)
lstm_main(const float* __restrict__ b0g,
          const float* __restrict__ b1g,
          const float* __restrict__ Wp,
          const float* __restrict__ bp,
          float* __restrict__ out)
{
    extern __shared__ __align__(256) unsigned char smem[];
    unsigned char* s_w   = smem;             // 6*8192 + 8*8192 = 114688
    unsigned char* s_act = smem + 114688;    // 3 x 32768 = 98304 -> total 212992

    const int tid  = threadIdx.x;
    const int lane = tid & 31;
    const int warp = tid >> 5;
    const int cta  = blockIdx.x;
    const int jt   = cta >> 1;               // col tile (32 cols)
    const int bh   = cta & 1;                // batch half (64 batches)
    const int u    = lane >> 2;              // unit 0..7 within CTA

    // preload weights (f16, pre-swizzled): 48KB + 64KB, linear cp.async
    {
        const unsigned char* w0 = &g_W0s[jt][0][0];
        const unsigned char* w1 = &g_W1s[jt][0][0];
        #pragma unroll
        for (int i = 0; i < 12; i++) { int o = (tid + (i << 8)) << 4; cp16(s_w + o, w0 + o); }
        #pragma unroll
        for (int i = 0; i < 16; i++) { int o = (tid + (i << 8)) << 4; cp16(s_w + 49152 + o, w1 + o); }
        cp_commit();
        CP_WAIT0();
    }
    __syncthreads();

    const int jb = jt * 8 + u;
    const float4 bias0 = make_float4(b0g[jb], b0g[512 + jb], b0g[1024 + jb], b0g[1536 + jb]);
    const float4 bias1 = make_float4(b1g[jb], b1g[512 + jb], b1g[1024 + jb], b1g[1536 + jb]);

    float c0r[2] = {0.f, 0.f};
    float c1r[2] = {0.f, 0.f};
    float acc[8];

    const u32 actbase = smem_u32(s_act);
    const u32 wb0 = smem_u32(s_w);
    const u32 wb1 = wb0 + 49152u;
    const u32 cj = (u32)((jt * 8) & 127) >> 3;
    const int htile = (jt * 8) >> 7;
    const u32 boff = (u32)bh << 14;          // 16KB batch-half byte offset in act tiles

    LaneCtx L;
    L.sA  = (u32)(lane & 7);
    L.rA  = (u32)((((lane >> 3) & 1) << 3) | (lane & 7));
    L.kgA = (u32)(lane >> 4);
    L.rB  = (u32)((lane & 7) + warp * 8);
    L.kgB = (u32)((lane >> 3) & 1);

    int sbuf = 0, cbuf = 0;

    // ---- bootstrap: L0(0) = [x(0) | h0_init(buf1, zeros)] ----
    stage32(s_act + sbuf * 32768, &g_xs[0][0][boff], &g_xs[0][1][boff], tid); ADV3(sbuf);
    stage32(s_act + sbuf * 32768, &g_h0s[1][0][boff], &g_h0s[1][1][boff], tid); ADV3(sbuf);
    ACCZ(acc);
    CP_WAIT1(); __syncthreads();
    stage32(s_act + sbuf * 32768, &g_h0s[1][2][boff], &g_h0s[1][3][boff], tid); ADV3(sbuf);
    mma2(actbase + (u32)cbuf * 32768u, wb0 + 0u, acc, L); ADV3(cbuf);
    CP_WAIT1(); __syncthreads();
    mma2(actbase + (u32)cbuf * 32768u, wb0 + 16384u, acc, L); ADV3(cbuf);
    CP_WAIT0(); __syncthreads();
    mma2(actbase + (u32)cbuf * 32768u, wb0 + 32768u, acc, L); ADV3(cbuf);
    epilogue(acc, c0r, bias0, &g_h0s[0][htile][0], cj, lane, warp, u, bh);
    __syncthreads();

    for (int t = 0; t < S_; t++) {
        const int cur = t & 1, prv = cur ^ 1;
        const bool notlast = (t + 1 < S_);

        grid_sync_flag(cta, tid, (unsigned)(t + 1));   // h0(t), h1(t-1) final everywhere

        // ---- L1(t): groups [h1p01, h1p23, h0c01, h0c23]; prefetch L0(t+1) G0,G1 ----
        // W1 K-layout: chunks 0-3 = h0 rows, chunks 4-7 = h1_prev rows.
        // Staging order is h1p-first, so weight offsets are swapped accordingly:
        //   h1p01 -> wb1+32768 (chunks 4,5), h1p23 -> wb1+49152 (chunks 6,7),
        //   h0c01 -> wb1+0     (chunks 0,1), h0c23 -> wb1+16384 (chunks 2,3).
        stage32(s_act + sbuf * 32768, &g_h1s[prv][0][boff], &g_h1s[prv][1][boff], tid); ADV3(sbuf);
        stage32(s_act + sbuf * 32768, &g_h1s[prv][2][boff], &g_h1s[prv][3][boff], tid); ADV3(sbuf);
        ACCZ(acc);
        CP_WAIT1(); __syncthreads();
        stage32(s_act + sbuf * 32768, &g_h0s[cur][0][boff], &g_h0s[cur][1][boff], tid); ADV3(sbuf);
        mma2(actbase + (u32)cbuf * 32768u, wb1 + 32768u, acc, L); ADV3(cbuf);
        CP_WAIT1(); __syncthreads();
        stage32(s_act + sbuf * 32768, &g_h0s[cur][2][boff], &g_h0s[cur][3][boff], tid); ADV3(sbuf);
        mma2(actbase + (u32)cbuf * 32768u, wb1 + 49152u, acc, L); ADV3(cbuf);
        CP_WAIT1(); __syncthreads();
        if (notlast) { stage32(s_act + sbuf * 32768, &g_xs[t + 1][0][boff], &g_xs[t + 1][1][boff], tid); ADV3(sbuf); }
        mma2(actbase + (u32)cbuf * 32768u, wb1 + 0u, acc, L); ADV3(cbuf);
        if (notlast) { CP_WAIT1(); } else { CP_WAIT0(); }
        __syncthreads();
        if (notlast) { stage32(s_act + sbuf * 32768, &g_h0s[cur][0][boff], &g_h0s[cur][1][boff], tid); ADV3(sbuf); }
        mma2(actbase + (u32)cbuf * 32768u, wb1 + 16384u, acc, L); ADV3(cbuf);
        epilogue(acc, c1r, bias1, &g_h1s[cur][htile][0], cj, lane, warp, u, bh);
        __syncthreads();

        // ---- L0(t+1): groups [x(t+1) (staged), h0(t)01 (staged), h0(t)23] ----
        if (notlast) {
            ACCZ(acc);
            CP_WAIT1(); __syncthreads();
            stage32(s_act + sbuf * 32768, &g_h0s[cur][2][boff], &g_h0s[cur][3][boff], tid); ADV3(sbuf);
            mma2(actbase + (u32)cbuf * 32768u, wb0 + 0u, acc, L); ADV3(cbuf);
            CP_WAIT1(); __syncthreads();
            mma2(actbase + (u32)cbuf * 32768u, wb0 + 16384u, acc, L); ADV3(cbuf);
            CP_WAIT0(); __syncthreads();
            mma2(actbase + (u32)cbuf * 32768u, wb0 + 32768u, acc, L); ADV3(cbuf);
            // h0(t+1) -> buffer (t+1)&1 = prv
            epilogue(acc, c0r, bias0, &g_h0s[prv][htile][0], cj, lane, warp, u, bh);
            __syncthreads();
        }
    }

    grid_sync_flag(cta, tid, (unsigned)(S_ + 1));

    // ---- projection: out[b][m] = sum_j h1[b][j] * Wp[j][m] + bp[m] ----
    {
        const unsigned char* h1b = &g_h1s[1][0][0];   // buf 1 (t = 511)
        int mstart = cta * 10;
        int mend = mstart + 10; if (mend > ODIM) mend = ODIM;
        int b  = tid & 127;
        int mq = tid >> 7;     // 0..1
        for (int m = mstart + mq; m < mend; m += 2) {
            float a = bp[m];
            for (int k = 0; k < H_; k++) {
                u32 off = swzoff(b, k & 127);
                a += __half2float(*(const __half*)(h1b + (size_t)(k >> 7) * 32768 + off))
                     * Wp[k * ODIM + m];
            }
            out[b * ODIM + m] = a;
        }
    }
}

// ---------------- entry ----------------
extern "C" void kernel_launch(void* const* d_in, const int* in_sizes, int n_in,
                              void* d_out, int out_size)
{
    const float* x  = (const float*)d_in[0];
    const float* W0 = (const float*)d_in[1];
    const float* b0 = (const float*)d_in[2];
    const float* W1 = (const float*)d_in[3];
    const float* b1 = (const float*)d_in[4];
    const float* Wp = (const float*)d_in[5];
    const float* bp = (const float*)d_in[6];
    float* out = (float*)d_out;

    cudaFuncSetAttribute(lstm_main, cudaFuncAttributeMaxDynamicSharedMemorySize, 212992);

    prep_kernel<<<2048, 256>>>(x, W0, W1);
    lstm_main<<<NCTA, 256, 212992>>>(b0, b1, Wp, bp, out);
}